// round 8
// baseline (speedup 1.0000x reference)
#include <cuda_runtime.h>

#define BATCH 32
#define DIM 96
#define HH 128
#define WW 128
#define CR 24            // DIM / 4
#define KK 9             // 3x3
#define PLANE_ELEMS (HH * WW)          // 16384
#define PLANE_F4 (PLANE_ELEMS / 4)     // 4096
#define NPLANES (BATCH * DIM)          // 3072
#define BN_EPS 1e-5f

#define QPP 4                          // quarters per plane
#define ROWS_PB 32                     // rows per block
#define SROWS (ROWS_PB + 2)            // 34 (row halo)
#define NBLOCKS (NPLANES * QPP)        // 12288

// scratch (no allocations allowed)
__device__ float g_partial[NPLANES * QPP];
__device__ float g_pooled[NPLANES];
__device__ int   g_pcnt[NPLANES];
__device__ int   g_scnt[BATCH];

__global__ void init_kernel() {
    const int i = blockIdx.x * 256 + threadIdx.x;
    if (i < NPLANES) g_pcnt[i] = 0;
    if (i < BATCH)   g_scnt[i] = 0;
}

// ---------------------------------------------------------------------------
// Fused single-read kernel. One block per (plane, 32-row quarter).
//   smem <- 34 rows of x (halo incl.)  [the ONLY DRAM read of x]
//   partial pool over own 32 rows -> plane combine (fixed order) -> sample cnt
//   spin until sample's 96 planes pooled -> weight gen -> conv from smem.
// ---------------------------------------------------------------------------
__global__ __launch_bounds__(256) void fused_kernel(const float* __restrict__ x,
                                                    const float* __restrict__ w1,
                                                    const float* __restrict__ gamma,
                                                    const float* __restrict__ beta,
                                                    const float* __restrict__ rmean,
                                                    const float* __restrict__ rvar,
                                                    const float* __restrict__ w2,
                                                    const float* __restrict__ b2,
                                                    const float* __restrict__ bias,
                                                    float* __restrict__ out) {
    __shared__ float4 s4[SROWS * 32];            // 17408 B
    __shared__ float warp_sums[8];
    __shared__ float pooled_s[DIM];
    __shared__ float h1_s[CR];
    __shared__ float wsh[KK];
    __shared__ float bsh;

    const int bid    = blockIdx.x;
    const int plane  = bid >> 2;
    const int q      = bid & 3;
    const int sample = plane / DIM;
    const int c      = plane % DIM;
    const int r0     = q * ROWS_PB;
    const int tid    = threadIdx.x;

    const float4* __restrict__ x4 = (const float4*)(x) + (size_t)plane * PLANE_F4;
    const float4 zero4 = make_float4(0.f, 0.f, 0.f, 0.f);

    // ---- 1. load 34 rows into smem (zeros outside the plane) ----
#pragma unroll
    for (int i = tid; i < SROWS * 32; i += 256) {
        const int sr = i >> 5, c4 = i & 31;
        const int gr = r0 + sr - 1;
        float4 v = zero4;
        if (gr >= 0 && gr < HH) v = x4[gr * 32 + c4];
        s4[i] = v;
    }
    __syncthreads();

    // ---- 2. partial pool over own rows (smem rows 1..32) ----
    float acc = 0.f;
#pragma unroll
    for (int i = 0; i < 4; i++) {
        float4 v = s4[32 + tid + 256 * i];
        acc += (v.x + v.y) + (v.z + v.w);
    }
#pragma unroll
    for (int off = 16; off > 0; off >>= 1)
        acc += __shfl_xor_sync(0xffffffffu, acc, off);
    if ((tid & 31) == 0) warp_sums[tid >> 5] = acc;
    __syncthreads();

    if (tid == 0) {
        float s = 0.f;
#pragma unroll
        for (int w = 0; w < 8; w++) s += warp_sums[w];
        __stcg(&g_partial[plane * QPP + q], s);
        __threadfence();
        if (atomicAdd(&g_pcnt[plane], 1) == QPP - 1) {
            // last quarter of this plane: combine in FIXED order (deterministic)
            float t = 0.f;
#pragma unroll
            for (int k = 0; k < QPP; k++) t += __ldcg(&g_partial[plane * QPP + k]);
            __stcg(&g_pooled[plane], t * (1.0f / (float)PLANE_ELEMS));
            __threadfence();
            atomicAdd(&g_scnt[sample], 1);
        }
    }

    // ---- 3. wait for the sample's 96 plane means ----
    if (tid == 0) {
        volatile int* cnt = &g_scnt[sample];
        while (*cnt < DIM) __nanosleep(64);
    }
    __syncthreads();

    // ---- 4. weight generation (redundant per block; tiny) ----
    if (tid < DIM) pooled_s[tid] = __ldcg(&g_pooled[sample * DIM + tid]);
    __syncthreads();

    if (tid < CR) {
        const float* wrow = w1 + tid * DIM;
        float a = 0.f;
#pragma unroll 8
        for (int i = 0; i < DIM; i++) a += pooled_s[i] * wrow[i];
        float z = (a - rmean[tid]) * rsqrtf(rvar[tid] + BN_EPS) * gamma[tid] + beta[tid];
        h1_s[tid] = 1.0f / (1.0f + __expf(-z));
    }
    __syncthreads();

    if (tid < KK) {
        const float* wrow = w2 + (c * KK + tid) * CR;
        float a = b2[c * KK + tid];
#pragma unroll
        for (int i = 0; i < CR; i++) a += h1_s[i] * wrow[i];
        wsh[tid] = a;
    }
    if (tid == KK) bsh = bias[c];
    __syncthreads();

    // ---- 5. conv from smem: warp w -> 4 rows; SHFL column halo ----
    const float w00 = wsh[0], w01 = wsh[1], w02 = wsh[2];
    const float w10 = wsh[3], w11 = wsh[4], w12 = wsh[5];
    const float w20 = wsh[6], w21 = wsh[7], w22 = wsh[8];
    const float bv = bsh;

    const int w  = tid >> 5;          // 0..7
    const int tx = tid & 31;
    const int sr0 = w * 4;            // smem row of window-top for first output

    float4* __restrict__ out4 = (float4*)(out) + (size_t)plane * PLANE_F4;

    float4 vA = s4[(sr0 + 0) * 32 + tx];
    float4 vB = s4[(sr0 + 1) * 32 + tx];
    float lA = __shfl_up_sync(0xffffffffu, vA.w, 1);
    float rA = __shfl_down_sync(0xffffffffu, vA.x, 1);
    float lB = __shfl_up_sync(0xffffffffu, vB.w, 1);
    float rB = __shfl_down_sync(0xffffffffu, vB.x, 1);
    if (tx == 0)  { lA = 0.f; lB = 0.f; }
    if (tx == 31) { rA = 0.f; rB = 0.f; }

#pragma unroll
    for (int i = 0; i < 4; i++) {
        float4 vC = s4[(sr0 + 2 + i) * 32 + tx];
        float lC = __shfl_up_sync(0xffffffffu, vC.w, 1);
        float rC = __shfl_down_sync(0xffffffffu, vC.x, 1);
        if (tx == 0)  lC = 0.f;
        if (tx == 31) rC = 0.f;

        float4 o;
        o.x = bv + w00 * lA   + w01 * vA.x + w02 * vA.y
                 + w10 * lB   + w11 * vB.x + w12 * vB.y
                 + w20 * lC   + w21 * vC.x + w22 * vC.y;
        o.y = bv + w00 * vA.x + w01 * vA.y + w02 * vA.z
                 + w10 * vB.x + w11 * vB.y + w12 * vB.z
                 + w20 * vC.x + w21 * vC.y + w22 * vC.z;
        o.z = bv + w00 * vA.y + w01 * vA.z + w02 * vA.w
                 + w10 * vB.y + w11 * vB.z + w12 * vB.w
                 + w20 * vC.y + w21 * vC.z + w22 * vC.w;
        o.w = bv + w00 * vA.z + w01 * vA.w + w02 * rA
                 + w10 * vB.z + w11 * vB.w + w12 * rB
                 + w20 * vC.z + w21 * vC.w + w22 * rC;

        out4[(r0 + w * 4 + i) * 32 + tx] = o;

        vA = vB; lA = lB; rA = rB;
        vB = vC; lB = lC; rB = rC;
    }
}

// ---------------------------------------------------------------------------
extern "C" void kernel_launch(void* const* d_in, const int* in_sizes, int n_in,
                              void* d_out, int out_size) {
    const float* x     = (const float*)d_in[0];
    const float* w1    = (const float*)d_in[1];
    const float* gamma = (const float*)d_in[2];
    const float* beta  = (const float*)d_in[3];
    const float* rmean = (const float*)d_in[4];
    const float* rvar  = (const float*)d_in[5];
    const float* w2    = (const float*)d_in[6];
    const float* b2    = (const float*)d_in[7];
    const float* bias  = (const float*)d_in[8];
    float* out = (float*)d_out;

    init_kernel<<<(NPLANES + 255) / 256, 256>>>();
    fused_kernel<<<NBLOCKS, 256>>>(x, w1, gamma, beta, rmean, rvar,
                                   w2, b2, bias, out);
}

// round 9
// speedup vs baseline: 1.9658x; 1.9658x over previous
#include <cuda_runtime.h>

#define BATCH 32
#define DIM 96
#define HH 128
#define WW 128
#define CR 24            // DIM / 4
#define KK 9             // 3x3
#define PLANE_ELEMS (HH * WW)          // 16384
#define PLANE_F4 (PLANE_ELEMS / 4)     // 4096
#define NPLANES (BATCH * DIM)          // 3072
#define BN_EPS 1e-5f

// scratch (no allocations allowed)
__device__ float g_pooled[NPLANES];          // [b][c] mean

// ---------------------------------------------------------------------------
// Kernel 1: global average pool per (b,c) plane. One block per plane.
// 81% DRAM — at ceiling; unchanged. Ascending order warms L2 tail for dwconv.
// ---------------------------------------------------------------------------
__global__ void pool_kernel(const float* __restrict__ x) {
    const int plane = blockIdx.x;
    const float4* __restrict__ x4 = (const float4*)(x) + (size_t)plane * PLANE_F4;
    const int tid = threadIdx.x;

    float acc = 0.f;
#pragma unroll 4
    for (int i = tid; i < PLANE_F4; i += 256) {
        float4 v = x4[i];
        acc += (v.x + v.y) + (v.z + v.w);
    }
#pragma unroll
    for (int off = 16; off > 0; off >>= 1)
        acc += __shfl_xor_sync(0xffffffffu, acc, off);

    __shared__ float warp_sums[8];
    if ((tid & 31) == 0) warp_sums[tid >> 5] = acc;
    __syncthreads();
    if (tid == 0) {
        float s = 0.f;
#pragma unroll
        for (int w = 0; w < 8; w++) s += warp_sums[w];
        g_pooled[plane] = s * (1.0f / (float)PLANE_ELEMS);
    }
}

// ---------------------------------------------------------------------------
// Kernel 2: fused weight-gen + depthwise 3x3 (stride 1, pad 1).
// One 128-thread block per plane (reversed order). Prologue: redundant tiny
// weight-gen (h1 + this channel's 9 taps). Main: 4 warps, each a 32-row chunk,
// register sliding window fed by coalesced LDG.128 straight from global;
// column halo via SHFL (lane 0/31 edges are the true zero pad).
// launch_bounds(128,12) caps regs (~42) -> 1536 thr/SM for more MLP.
// ---------------------------------------------------------------------------
__global__ __launch_bounds__(128, 12) void dwconv_kernel(const float* __restrict__ x,
                                                         const float* __restrict__ w1,
                                                         const float* __restrict__ gamma,
                                                         const float* __restrict__ beta,
                                                         const float* __restrict__ rmean,
                                                         const float* __restrict__ rvar,
                                                         const float* __restrict__ w2,
                                                         const float* __restrict__ b2,
                                                         const float* __restrict__ bias,
                                                         float* __restrict__ out) {
    const int plane  = (NPLANES - 1) - blockIdx.x;   // reversed for L2-tail hits
    const int sample = plane / DIM;
    const int c      = plane % DIM;
    const int tid    = threadIdx.x;

    __shared__ float pooled_s[DIM];
    __shared__ float h1_s[CR];
    __shared__ float wsh[KK];
    __shared__ float bsh;

    // ---- prologue: weight generation (redundant per block; tiny) ----
    if (tid < DIM) pooled_s[tid] = g_pooled[sample * DIM + tid];
    __syncthreads();

    if (tid < CR) {
        const float* wrow = w1 + tid * DIM;
        float a = 0.f;
#pragma unroll 8
        for (int i = 0; i < DIM; i++) a += pooled_s[i] * wrow[i];
        float z = (a - rmean[tid]) * rsqrtf(rvar[tid] + BN_EPS) * gamma[tid] + beta[tid];
        h1_s[tid] = 1.0f / (1.0f + __expf(-z));
    }
    __syncthreads();

    if (tid < KK) {
        const float* wrow = w2 + (c * KK + tid) * CR;
        float a = b2[c * KK + tid];
#pragma unroll
        for (int i = 0; i < CR; i++) a += h1_s[i] * wrow[i];
        wsh[tid] = a;
    }
    if (tid == KK) bsh = bias[c];
    __syncthreads();

    // ---- conv: warp w -> 32-row chunk ----
    const int w  = tid >> 5;       // 0..3
    const int tx = tid & 31;
    const int r0 = w * 32;

    const float4* __restrict__ x4   = (const float4*)(x) + (size_t)plane * PLANE_F4;
    float4*       __restrict__ out4 = (float4*)(out)     + (size_t)plane * PLANE_F4;

    const float w00 = wsh[0], w01 = wsh[1], w02 = wsh[2];
    const float w10 = wsh[3], w11 = wsh[4], w12 = wsh[5];
    const float w20 = wsh[6], w21 = wsh[7], w22 = wsh[8];
    const float bv = bsh;

    const float4 zero4 = make_float4(0.f, 0.f, 0.f, 0.f);

    float4 vA = (r0 == 0) ? zero4 : x4[(r0 - 1) * 32 + tx];
    float4 vB = x4[r0 * 32 + tx];
    float lA = __shfl_up_sync(0xffffffffu, vA.w, 1);
    float rA = __shfl_down_sync(0xffffffffu, vA.x, 1);
    float lB = __shfl_up_sync(0xffffffffu, vB.w, 1);
    float rB = __shfl_down_sync(0xffffffffu, vB.x, 1);
    if (tx == 0)  { lA = 0.f; lB = 0.f; }
    if (tx == 31) { rA = 0.f; rB = 0.f; }

#pragma unroll 4
    for (int i = 0; i < 32; i++) {
        const int rn = r0 + i + 1;
        float4 vC = (rn < HH) ? x4[rn * 32 + tx] : zero4;
        float lC = __shfl_up_sync(0xffffffffu, vC.w, 1);
        float rC = __shfl_down_sync(0xffffffffu, vC.x, 1);
        if (tx == 0)  lC = 0.f;
        if (tx == 31) rC = 0.f;

        float4 o;
        o.x = bv + w00 * lA   + w01 * vA.x + w02 * vA.y
                 + w10 * lB   + w11 * vB.x + w12 * vB.y
                 + w20 * lC   + w21 * vC.x + w22 * vC.y;
        o.y = bv + w00 * vA.x + w01 * vA.y + w02 * vA.z
                 + w10 * vB.x + w11 * vB.y + w12 * vB.z
                 + w20 * vC.x + w21 * vC.y + w22 * vC.z;
        o.z = bv + w00 * vA.y + w01 * vA.z + w02 * vA.w
                 + w10 * vB.y + w11 * vB.z + w12 * vB.w
                 + w20 * vC.y + w21 * vC.z + w22 * vC.w;
        o.w = bv + w00 * vA.z + w01 * vA.w + w02 * rA
                 + w10 * vB.z + w11 * vB.w + w12 * rB
                 + w20 * vC.z + w21 * vC.w + w22 * rC;

        out4[(r0 + i) * 32 + tx] = o;

        vA = vB; lA = lB; rA = rB;
        vB = vC; lB = lC; rB = rC;
    }
}

// ---------------------------------------------------------------------------
extern "C" void kernel_launch(void* const* d_in, const int* in_sizes, int n_in,
                              void* d_out, int out_size) {
    const float* x     = (const float*)d_in[0];
    const float* w1    = (const float*)d_in[1];
    const float* gamma = (const float*)d_in[2];
    const float* beta  = (const float*)d_in[3];
    const float* rmean = (const float*)d_in[4];
    const float* rvar  = (const float*)d_in[5];
    const float* w2    = (const float*)d_in[6];
    const float* b2    = (const float*)d_in[7];
    const float* bias  = (const float*)d_in[8];
    float* out = (float*)d_out;

    pool_kernel<<<NPLANES, 256>>>(x);
    dwconv_kernel<<<NPLANES, 128>>>(x, w1, gamma, beta, rmean, rvar,
                                    w2, b2, bias, out);
}

// round 10
// speedup vs baseline: 2.1256x; 1.0813x over previous
#include <cuda_runtime.h>

#define BATCH 32
#define DIM 96
#define HH 128
#define WW 128
#define CR 24            // DIM / 4
#define KK 9             // 3x3
#define PLANE_ELEMS (HH * WW)          // 16384
#define PLANE_F4 (PLANE_ELEMS / 4)     // 4096
#define NPLANES (BATCH * DIM)          // 3072
#define BN_EPS 1e-5f

// scratch (no allocations allowed)
__device__ float g_pooled[NPLANES];          // [b][c] mean
__device__ float g_wdyn[NPLANES * KK];       // [b][c][3][3]

// ---------------------------------------------------------------------------
// Kernel 1: global average pool per (b,c) plane. One block per plane.
// 81% DRAM — at ceiling; unchanged.
// ---------------------------------------------------------------------------
__global__ void pool_kernel(const float* __restrict__ x) {
    const int plane = blockIdx.x;
    const float4* __restrict__ x4 = (const float4*)(x) + (size_t)plane * PLANE_F4;
    const int tid = threadIdx.x;

    float acc = 0.f;
#pragma unroll 4
    for (int i = tid; i < PLANE_F4; i += 256) {
        float4 v = x4[i];
        acc += (v.x + v.y) + (v.z + v.w);
    }
#pragma unroll
    for (int off = 16; off > 0; off >>= 1)
        acc += __shfl_xor_sync(0xffffffffu, acc, off);

    __shared__ float warp_sums[8];
    if ((tid & 31) == 0) warp_sums[tid >> 5] = acc;
    __syncthreads();
    if (tid == 0) {
        float s = 0.f;
#pragma unroll
        for (int w = 0; w < 8; w++) s += warp_sums[w];
        g_pooled[plane] = s * (1.0f / (float)PLANE_ELEMS);
    }
}

// ---------------------------------------------------------------------------
// Kernel 2: dynamic weight generation. One block per batch sample. (~2 us)
// ---------------------------------------------------------------------------
__global__ void weight_kernel(const float* __restrict__ w1,      // [CR, DIM]
                              const float* __restrict__ gamma,
                              const float* __restrict__ beta,
                              const float* __restrict__ rmean,
                              const float* __restrict__ rvar,
                              const float* __restrict__ w2,      // [DIM*KK, CR]
                              const float* __restrict__ b2) {
    const int b = blockIdx.x;
    const int tid = threadIdx.x;   // 128 threads

    __shared__ float pooled_s[DIM];
    __shared__ float h1_s[CR];

    if (tid < DIM) pooled_s[tid] = g_pooled[b * DIM + tid];
    __syncthreads();

    if (tid < CR) {
        float acc = 0.f;
        const float* wrow = w1 + tid * DIM;
#pragma unroll 8
        for (int i = 0; i < DIM; i++) acc += pooled_s[i] * wrow[i];
        float z = (acc - rmean[tid]) * rsqrtf(rvar[tid] + BN_EPS) * gamma[tid] + beta[tid];
        h1_s[tid] = 1.0f / (1.0f + __expf(-z));
    }
    __syncthreads();

    const int nout = DIM * KK;  // 864
    for (int o = tid; o < nout; o += 128) {
        const float* wrow = w2 + o * CR;
        float acc = b2[o];
#pragma unroll
        for (int i = 0; i < CR; i++) acc += h1_s[i] * wrow[i];
        g_wdyn[b * nout + o] = acc;
    }
}

// ---------------------------------------------------------------------------
// Kernel 3: per-sample depthwise 3x3, stride 1, pad 1 — register window, no
// smem. One WARP per (plane, 32-row chunk); lane tx owns cols [4tx,4tx+4).
// Explicit prefetch 2 rows ahead + unroll 8 for deep MLP. Column halo via
// SHFL; lane 0/31 edges are the true zero pad. Reversed plane order reuses
// pool's L2 tail.
// ---------------------------------------------------------------------------
#define CHUNKS 4
#define CHUNK_H (HH / CHUNKS)   // 32

__global__ __launch_bounds__(128) void dwconv_kernel(const float* __restrict__ x,
                                                     const float* __restrict__ bias,
                                                     float* __restrict__ out) {
    const int wid = threadIdx.x >> 5;
    const int tx  = threadIdx.x & 31;
    const int lin = blockIdx.x * 4 + wid;          // 0 .. NPLANES*CHUNKS-1
    const int plane = (NPLANES - 1) - (lin >> 2);  // reversed plane order
    const int chunk = lin & 3;
    const int c = plane % DIM;
    const int r0 = chunk * CHUNK_H;

    const float4* __restrict__ x4   = (const float4*)(x) + (size_t)plane * PLANE_F4;
    float4*       __restrict__ out4 = (float4*)(out)     + (size_t)plane * PLANE_F4;

    const float* wp = g_wdyn + plane * KK;         // uniform -> broadcast loads
    const float w00 = wp[0], w01 = wp[1], w02 = wp[2];
    const float w10 = wp[3], w11 = wp[4], w12 = wp[5];
    const float w20 = wp[6], w21 = wp[7], w22 = wp[8];
    const float bv = bias[c];

    const float4 zero4 = make_float4(0.f, 0.f, 0.f, 0.f);

    // window rows: A = r-1, B = r, C = r+1 ; pre = r+2 (prefetch)
    float4 vA = (r0 == 0) ? zero4 : x4[(r0 - 1) * 32 + tx];
    float4 vB = x4[r0 * 32 + tx];
    float4 vC = (r0 + 1 < HH) ? x4[(r0 + 1) * 32 + tx] : zero4;
    float4 pre = (r0 + 2 < HH) ? x4[(r0 + 2) * 32 + tx] : zero4;

    float lA = __shfl_up_sync(0xffffffffu, vA.w, 1);
    float rA = __shfl_down_sync(0xffffffffu, vA.x, 1);
    float lB = __shfl_up_sync(0xffffffffu, vB.w, 1);
    float rB = __shfl_down_sync(0xffffffffu, vB.x, 1);
    if (tx == 0)  { lA = 0.f; lB = 0.f; }
    if (tx == 31) { rA = 0.f; rB = 0.f; }

#pragma unroll 8
    for (int i = 0; i < CHUNK_H; i++) {
        float lC = __shfl_up_sync(0xffffffffu, vC.w, 1);
        float rC = __shfl_down_sync(0xffffffffu, vC.x, 1);
        if (tx == 0)  lC = 0.f;
        if (tx == 31) rC = 0.f;

        float4 o;
        o.x = bv + w00 * lA   + w01 * vA.x + w02 * vA.y
                 + w10 * lB   + w11 * vB.x + w12 * vB.y
                 + w20 * lC   + w21 * vC.x + w22 * vC.y;
        o.y = bv + w00 * vA.x + w01 * vA.y + w02 * vA.z
                 + w10 * vB.x + w11 * vB.y + w12 * vB.z
                 + w20 * vC.x + w21 * vC.y + w22 * vC.z;
        o.z = bv + w00 * vA.y + w01 * vA.z + w02 * vA.w
                 + w10 * vB.y + w11 * vB.z + w12 * vB.w
                 + w20 * vC.y + w21 * vC.z + w22 * vC.w;
        o.w = bv + w00 * vA.z + w01 * vA.w + w02 * rA
                 + w10 * vB.z + w11 * vB.w + w12 * rB
                 + w20 * vC.z + w21 * vC.w + w22 * rC;

        out4[(r0 + i) * 32 + tx] = o;

        // slide window; issue next prefetch (r0+i+3)
        vA = vB; lA = lB; rA = rB;
        vB = vC; lB = lC; rB = rC;
        vC = pre;
        const int rp = r0 + i + 3;
        pre = (rp < HH) ? x4[rp * 32 + tx] : zero4;
    }
}

// ---------------------------------------------------------------------------
extern "C" void kernel_launch(void* const* d_in, const int* in_sizes, int n_in,
                              void* d_out, int out_size) {
    const float* x     = (const float*)d_in[0];
    const float* w1    = (const float*)d_in[1];
    const float* gamma = (const float*)d_in[2];
    const float* beta  = (const float*)d_in[3];
    const float* rmean = (const float*)d_in[4];
    const float* rvar  = (const float*)d_in[5];
    const float* w2    = (const float*)d_in[6];
    const float* b2    = (const float*)d_in[7];
    const float* bias  = (const float*)d_in[8];
    float* out = (float*)d_out;

    pool_kernel<<<NPLANES, 256>>>(x);
    weight_kernel<<<BATCH, 128>>>(w1, gamma, beta, rmean, rvar, w2, b2);
    dwconv_kernel<<<NPLANES * CHUNKS / 4, 128>>>(x, bias, out);
}